// round 13
// baseline (speedup 1.0000x reference)
#include <cuda_runtime.h>
#include <cuda_fp16.h>
#include <cstdint>

#define B_ 8
#define C_ 32
#define N_ 4096
#define KC 64
#define SPLIT 4

__device__ float g_e[B_ * N_];
__device__ float g_part[SPLIT][B_ * C_ * N_];
__device__ int g_cnt[4][32];   // [batch-pair][m-tile], zero-init, reset by epilogue

__global__ void mean_exp_kernel(const float* __restrict__ x) {
    int idx = blockIdx.x * blockDim.x + threadIdx.x;   // over B_*N_/4
    int b = idx >> 10;
    int n4 = (idx & 1023) << 2;
    const float* p = x + (((size_t)b * C_) << 12) + n4;
    float4 s = make_float4(0.f, 0.f, 0.f, 0.f);
#pragma unroll
    for (int c = 0; c < C_; c++) {
        float4 v = *reinterpret_cast<const float4*>(p + ((size_t)c << 12));
        s.x += v.x; s.y += v.y; s.z += v.z; s.w += v.w;
    }
    float4 e;
    e.x = __expf(s.x * (1.0f / C_));
    e.y = __expf(s.y * (1.0f / C_));
    e.z = __expf(s.z * (1.0f / C_));
    e.w = __expf(s.w * (1.0f / C_));
    reinterpret_cast<float4*>(g_e)[idx] = e;
}

__device__ __forceinline__ uint32_t pack_f16(float hi, float lo) {
    uint32_t d;
    asm("cvt.rn.f16x2.f32 %0, %1, %2;" : "=r"(d) : "f"(hi), "f"(lo));
    return d;
}
__device__ __forceinline__ uint32_t h2u(__half2 h) {
    return *reinterpret_cast<uint32_t*>(&h);
}

#define MMA_F16(acc, a, b0v, b1v)                                           \
    asm volatile(                                                           \
        "mma.sync.aligned.m16n8k16.row.col.f32.f16.f16.f32 "                \
        "{%0,%1,%2,%3}, {%4,%5,%6,%7}, {%8,%9}, {%0,%1,%2,%3};"             \
        : "+f"((acc)[0]), "+f"((acc)[1]), "+f"((acc)[2]), "+f"((acc)[3])    \
        : "r"((a)[0]), "r"((a)[1]), "r"((a)[2]), "r"((a)[3]),               \
          "r"(b0v), "r"(b1v))

__global__ __launch_bounds__(256, 2)
void gcn_mma_kernel(const float* __restrict__ x,
                    const float* __restrict__ adj,
                    const float* __restrict__ para,
                    float* __restrict__ out) {
    __shared__ uint32_t s_B[2][2][32 * 32];  // [buf][batch][c*32 + swz(npair)]
    __shared__ __half2 s_eh[2][KC];          // [buf][n] = (e_b0, e_b1)
    __shared__ int s_islast;

    const int tid = threadIdx.x;
    const int warp = tid >> 5;
    const int lane = tid & 31;
    const int q = lane >> 2;
    const int r = lane & 3;
    const int mb = blockIdx.x * 128 + warp * 16;
    const int bp = blockIdx.y;
    const int b0 = 2 * bp, b1 = 2 * bp + 1;
    const int z = blockIdx.z;
    const int nbeg = z * (N_ / SPLIT);
    const int nend = nbeg + (N_ / SPLIT);

    __half2 em_h2[2];
    em_h2[0] = __floats2half2_rn(g_e[b0 * N_ + mb + q],
                                 g_e[b1 * N_ + mb + q]);
    em_h2[1] = __floats2half2_rn(g_e[b0 * N_ + mb + q + 8],
                                 g_e[b1 * N_ + mb + q + 8]);

    float acc[2][4][4];
#pragma unroll
    for (int bi = 0; bi < 2; bi++)
#pragma unroll
        for (int cf = 0; cf < 4; cf++)
#pragma unroll
            for (int i = 0; i < 4; i++) acc[bi][cf][i] = 0.f;

    const int st_b = tid >> 7;
    const int st_c = (tid >> 2) & 31;
    const int st_p0 = (tid & 3) * 8;
    const float* st_x = x + (((size_t)(2 * bp + st_b) * C_ + st_c) << 12);
    const int st_sw = 4 * (st_c & 7);

#define STAGE_STORE(BUF, U, EV0, EV1)                                       \
    {                                                                       \
        uint32_t* dst = &s_B[BUF][st_b][st_c * 32];                         \
        uint32_t pr[8];                                                     \
        _Pragma("unroll")                                                   \
        for (int j = 0; j < 4; j++) {                                       \
            pr[2 * j]     = pack_f16(U[j].y, U[j].x);                       \
            pr[2 * j + 1] = pack_f16(U[j].w, U[j].z);                       \
        }                                                                   \
        *reinterpret_cast<uint4*>(&dst[(st_p0 + st_sw) & 31]) =             \
            make_uint4(pr[0], pr[1], pr[2], pr[3]);                         \
        *reinterpret_cast<uint4*>(&dst[(st_p0 + 4 + st_sw) & 31]) =         \
            make_uint4(pr[4], pr[5], pr[6], pr[7]);                         \
        if (tid < KC) s_eh[BUF][tid] = __floats2half2_rn(EV0, EV1);         \
    }

#define STAGE_LOAD(U, EV0, EV1, NBASE)                                      \
    {                                                                       \
        _Pragma("unroll")                                                   \
        for (int j = 0; j < 4; j++)                                         \
            U[j] = *reinterpret_cast<const float4*>(                        \
                st_x + (NBASE) + st_p0 * 2 + 4 * j);                        \
        if (tid < KC) {                                                     \
            EV0 = g_e[b0 * N_ + (NBASE) + tid];                             \
            EV1 = g_e[b1 * N_ + (NBASE) + tid];                             \
        }                                                                   \
    }

#define PRELOAD_ADJ(G, AP, KS)                                              \
    {                                                                       \
        const float* ab = (AP) + (size_t)((KS) * 16) * N_;                  \
        G[0][0] = __ldg(ab);                                                \
        G[0][1] = __ldg(ab + 8);                                            \
        G[1][0] = __ldg(ab + (size_t)N_);                                   \
        G[1][1] = __ldg(ab + (size_t)N_ + 8);                               \
        G[2][0] = __ldg(ab + (size_t)8 * N_);                               \
        G[2][1] = __ldg(ab + (size_t)8 * N_ + 8);                           \
        G[3][0] = __ldg(ab + (size_t)9 * N_);                               \
        G[3][1] = __ldg(ab + (size_t)9 * N_ + 8);                           \
    }

#define COMPUTE_KS(G, BUF, KS)                                              \
    {                                                                       \
        const int k0 = (KS) * 16;                                           \
        __half2 en[4];                                                      \
        en[0] = s_eh[BUF][k0 + 2 * r];                                      \
        en[1] = s_eh[BUF][k0 + 2 * r + 1];                                  \
        en[2] = s_eh[BUF][k0 + 2 * r + 8];                                  \
        en[3] = s_eh[BUF][k0 + 2 * r + 9];                                  \
        __half2 w[4][2];                                                    \
        _Pragma("unroll")                                                   \
        for (int kk = 0; kk < 4; kk++) {                                    \
            _Pragma("unroll")                                               \
            for (int mm = 0; mm < 2; mm++) {                                \
                __half2 e = em_h2[mm];                                      \
                __half2 d = __hadd2(en[kk], e);                             \
                __half2 mn = __hmin2(en[kk], e);                            \
                __half2 a2 = __float2half2_rn(G[kk][mm]);                   \
                w[kk][mm] = __hmul2(__hmul2(mn, h2rcp(d)), a2);             \
            }                                                               \
        }                                                                   \
        uint32_t a0[4], a1[4];                                              \
        a0[0] = h2u(__lows2half2(w[0][0], w[1][0]));                        \
        a0[1] = h2u(__lows2half2(w[0][1], w[1][1]));                        \
        a0[2] = h2u(__lows2half2(w[2][0], w[3][0]));                        \
        a0[3] = h2u(__lows2half2(w[2][1], w[3][1]));                        \
        a1[0] = h2u(__highs2half2(w[0][0], w[1][0]));                       \
        a1[1] = h2u(__highs2half2(w[0][1], w[1][1]));                       \
        a1[2] = h2u(__highs2half2(w[2][0], w[3][0]));                       \
        a1[3] = h2u(__highs2half2(w[2][1], w[3][1]));                       \
        const int kp0 = (KS) * 8;                                           \
        const int off0 = (kp0 + r + 4 * q) & 31;                            \
        const int off4 = (kp0 + r + 4 + 4 * q) & 31;                        \
        _Pragma("unroll")                                                   \
        for (int cf = 0; cf < 4; cf++) {                                    \
            const int row = (cf * 8 + q) * 32;                              \
            uint32_t b00 = s_B[BUF][0][row + off0];                         \
            uint32_t b01 = s_B[BUF][0][row + off4];                         \
            uint32_t b10 = s_B[BUF][1][row + off0];                         \
            uint32_t b11 = s_B[BUF][1][row + off4];                         \
            MMA_F16(acc[0][cf], a0, b00, b01);                              \
            MMA_F16(acc[1][cf], a1, b10, b11);                              \
        }                                                                   \
    }

    {
        float4 u[4];
        float ev0 = 0.f, ev1 = 0.f;
        STAGE_LOAD(u, ev0, ev1, nbeg);
        STAGE_STORE(0, u, ev0, ev1);
    }
    __syncthreads();

    int cur = 0;
    for (int n0 = nbeg; n0 < nend; n0 += KC) {
        const int n1 = n0 + KC;
        const bool has_next = (n1 < nend);

        float4 u[4];
        float ev0 = 0.f, ev1 = 0.f;
        if (has_next) STAGE_LOAD(u, ev0, ev1, n1);

        const float* ap = adj + (size_t)(n0 + 2 * r) * N_ + mb + q;
        float gA[4][2], gB[4][2];
        PRELOAD_ADJ(gA, ap, 0);
        PRELOAD_ADJ(gB, ap, 1);
        COMPUTE_KS(gA, cur, 0);
        PRELOAD_ADJ(gA, ap, 2);
        COMPUTE_KS(gB, cur, 1);
        PRELOAD_ADJ(gB, ap, 3);
        COMPUTE_KS(gA, cur, 2);
        COMPUTE_KS(gB, cur, 3);

        if (has_next) STAGE_STORE(cur ^ 1, u, ev0, ev1);
        __syncthreads();
        cur ^= 1;
    }

    // write this split's partial
#pragma unroll
    for (int bi = 0; bi < 2; bi++) {
        float* dst = g_part[z] + (((size_t)(2 * bp + bi) * C_) << 12);
#pragma unroll
        for (int cf = 0; cf < 4; cf++) {
            int c0 = cf * 8 + 2 * r;
            int m0 = mb + q;
            dst[((size_t)c0 << 12) + m0] = acc[bi][cf][0];
            dst[((size_t)(c0 + 1) << 12) + m0] = acc[bi][cf][1];
            dst[((size_t)c0 << 12) + m0 + 8] = acc[bi][cf][2];
            dst[((size_t)(c0 + 1) << 12) + m0 + 8] = acc[bi][cf][3];
        }
    }

    // last-arriving split CTA of this (bp, m-tile) does the epilogue
    __syncthreads();
    if (tid == 0) {
        __threadfence();
        int old = atomicAdd(&g_cnt[bp][blockIdx.x], 1);
        s_islast = (old == SPLIT - 1);
    }
    __syncthreads();
    if (s_islast) {
#pragma unroll
        for (int bi = 0; bi < 2; bi++) {
#pragma unroll
            for (int cf = 0; cf < 4; cf++) {
#pragma unroll
                for (int i = 0; i < 4; i++) {
                    int cc = cf * 8 + 2 * r + (i & 1);
                    int mm2 = mb + q + ((i & 2) ? 8 : 0);
                    size_t off = (((size_t)(2 * bp + bi) * C_ + cc) << 12) + mm2;
                    float s = g_part[0][off] + g_part[1][off] +
                              g_part[2][off] + g_part[3][off];
                    float pv = para[(cc << 12) + mm2];
                    out[off] = fmaxf(2.0f * s * pv, 0.f);
                }
            }
        }
        if (tid == 0) g_cnt[bp][blockIdx.x] = 0;   // reset for next graph replay
    }
}

extern "C" void kernel_launch(void* const* d_in, const int* in_sizes, int n_in,
                              void* d_out, int out_size) {
    const float* x    = (const float*)d_in[0];  // [8,32,64,64]
    const float* para = (const float*)d_in[1];  // [1,32,64,64]
    const float* adj  = (const float*)d_in[2];  // [4096,4096]
    float* out = (float*)d_out;

    mean_exp_kernel<<<B_ * N_ / 4 / 128, 128>>>(x);

    dim3 grid(N_ / 128, B_ / 2, SPLIT);
    gcn_mma_kernel<<<grid, 256>>>(x, adj, para, out);
}

// round 15
// speedup vs baseline: 1.2908x; 1.2908x over previous
#include <cuda_runtime.h>
#include <cuda_fp16.h>
#include <cstdint>

#define B_ 8
#define C_ 32
#define N_ 4096
#define KC 64
#define SPLIT 4

__device__ float g_e[B_ * N_];
__device__ float g_part[SPLIT][B_ * C_ * N_];

__global__ void mean_exp_kernel(const float* __restrict__ x) {
    int idx = blockIdx.x * blockDim.x + threadIdx.x;   // over B_*N_/4
    int b = idx >> 10;
    int n4 = (idx & 1023) << 2;
    const float* p = x + (((size_t)b * C_) << 12) + n4;
    float4 s = make_float4(0.f, 0.f, 0.f, 0.f);
#pragma unroll
    for (int c = 0; c < C_; c++) {
        float4 v = *reinterpret_cast<const float4*>(p + ((size_t)c << 12));
        s.x += v.x; s.y += v.y; s.z += v.z; s.w += v.w;
    }
    float4 e;
    e.x = __expf(s.x * (1.0f / C_));
    e.y = __expf(s.y * (1.0f / C_));
    e.z = __expf(s.z * (1.0f / C_));
    e.w = __expf(s.w * (1.0f / C_));
    reinterpret_cast<float4*>(g_e)[idx] = e;
}

__device__ __forceinline__ uint32_t pack_f16(float hi, float lo) {
    uint32_t d;
    asm("cvt.rn.f16x2.f32 %0, %1, %2;" : "=r"(d) : "f"(hi), "f"(lo));
    return d;
}
__device__ __forceinline__ uint32_t h2u(__half2 h) {
    return *reinterpret_cast<uint32_t*>(&h);
}
__device__ __forceinline__ void cp_async16(uint32_t saddr, const void* g) {
    asm volatile("cp.async.cg.shared.global [%0], [%1], 16;"
                 :: "r"(saddr), "l"(g) : "memory");
}
#define CP_COMMIT() asm volatile("cp.async.commit_group;" ::: "memory")
#define CP_WAIT0()  asm volatile("cp.async.wait_group 0;" ::: "memory")

#define MMA_F16(acc, a, b0v, b1v)                                           \
    asm volatile(                                                           \
        "mma.sync.aligned.m16n8k16.row.col.f32.f16.f16.f32 "                \
        "{%0,%1,%2,%3}, {%4,%5,%6,%7}, {%8,%9}, {%0,%1,%2,%3};"             \
        : "+f"((acc)[0]), "+f"((acc)[1]), "+f"((acc)[2]), "+f"((acc)[3])    \
        : "r"((a)[0]), "r"((a)[1]), "r"((a)[2]), "r"((a)[3]),               \
          "r"(b0v), "r"(b1v))

// All-static smem: adj ping-pong 2x16KB + single fea tile 8KB + s_eh 256B ≈ 41KB
__global__ __launch_bounds__(256, 2)
void gcn_mma_kernel(const float* __restrict__ x,
                    const float* __restrict__ adj) {
    __shared__ float s_adjf[2][32 * 128];    // [buf][row*128 + swz(col)]
    __shared__ uint32_t s_B[2][32 * 32];     // [batch][c*32 + swz(npair)]
    __shared__ __half2 s_eh[KC];             // [n] = (e_b0, e_b1)

    const int tid = threadIdx.x;
    const int warp = tid >> 5;
    const int lane = tid & 31;
    const int q = lane >> 2;
    const int r = lane & 3;
    const int mb_cta = blockIdx.x * 128;
    const int mb = mb_cta + warp * 16;
    const int ml0 = warp * 16 + q;           // local m col for rows q
    const int ml1 = ml0 + 8;                 // local m col for rows q+8
    const int bp = blockIdx.y;
    const int b0 = 2 * bp, b1 = 2 * bp + 1;
    const int z = blockIdx.z;
    const int nbeg = z * (N_ / SPLIT);
    const int nend = nbeg + (N_ / SPLIT);

    uint32_t s_adj_addr;
    asm("{ .reg .u64 t; cvta.to.shared.u64 t, %1; cvt.u32.u64 %0, t; }"
        : "=r"(s_adj_addr) : "l"(s_adjf));

    __half2 em_h2[2];
    em_h2[0] = __floats2half2_rn(g_e[b0 * N_ + mb + q],
                                 g_e[b1 * N_ + mb + q]);
    em_h2[1] = __floats2half2_rn(g_e[b0 * N_ + mb + q + 8],
                                 g_e[b1 * N_ + mb + q + 8]);

    float acc[2][4][4];
#pragma unroll
    for (int bi = 0; bi < 2; bi++)
#pragma unroll
        for (int cf = 0; cf < 4; cf++)
#pragma unroll
            for (int i = 0; i < 4; i++) acc[bi][cf][i] = 0.f;

    const int st_b = tid >> 7;
    const int st_c = (tid >> 2) & 31;
    const int st_p0 = (tid & 3) * 8;
    const float* st_x = x + (((size_t)(2 * bp + st_b) * C_ + st_c) << 12);
    const int st_sw = 4 * (st_c & 7);

    // cp.async adj staging: half H (32 rows x 128 cols) of chunk at N0 -> buffer BI
#define STAGE_ADJ(BI, H, N0)                                                \
    {                                                                       \
        const float* gsrc = adj + (size_t)((N0) + (H) * 32) * N_ + mb_cta;  \
        uint32_t sb = s_adj_addr + (BI) * 16384;                            \
        _Pragma("unroll")                                                   \
        for (int i = 0; i < 4; i++) {                                       \
            int lin = tid + i * 256;                                        \
            int row = lin >> 5, c4 = lin & 31;                              \
            int col = c4 * 4;                                               \
            int sw = col ^ (4 * (row & 7));                                 \
            cp_async16(sb + (uint32_t)(row * 128 + sw) * 4,                 \
                       gsrc + (size_t)row * N_ + col);                      \
        }                                                                   \
    }

#define STAGE_STORE(U, EV0, EV1)                                            \
    {                                                                       \
        uint32_t* dst = &s_B[st_b][st_c * 32];                              \
        uint32_t pr[8];                                                     \
        _Pragma("unroll")                                                   \
        for (int j = 0; j < 4; j++) {                                       \
            pr[2 * j]     = pack_f16(U[j].y, U[j].x);                       \
            pr[2 * j + 1] = pack_f16(U[j].w, U[j].z);                       \
        }                                                                   \
        *reinterpret_cast<uint4*>(&dst[(st_p0 + st_sw) & 31]) =             \
            make_uint4(pr[0], pr[1], pr[2], pr[3]);                         \
        *reinterpret_cast<uint4*>(&dst[(st_p0 + 4 + st_sw) & 31]) =         \
            make_uint4(pr[4], pr[5], pr[6], pr[7]);                         \
        if (tid < KC) s_eh[tid] = __floats2half2_rn(EV0, EV1);              \
    }

#define STAGE_LOAD(U, EV0, EV1, NBASE)                                      \
    {                                                                       \
        _Pragma("unroll")                                                   \
        for (int j = 0; j < 4; j++)                                         \
            U[j] = *reinterpret_cast<const float4*>(                        \
                st_x + (NBASE) + st_p0 * 2 + 4 * j);                        \
        if (tid < KC) {                                                     \
            EV0 = g_e[b0 * N_ + (NBASE) + tid];                             \
            EV1 = g_e[b1 * N_ + (NBASE) + tid];                             \
        }                                                                   \
    }

    // COMPUTE for kstep KS (0..3): adj from s_adjf buffer BA
#define COMPUTE_KS(BA, KS)                                                  \
    {                                                                       \
        const int k0 = (KS) * 16;                                           \
        const float* sa = s_adjf[BA];                                       \
        float G[4][2];                                                      \
        _Pragma("unroll")                                                   \
        for (int kk = 0; kk < 4; kk++) {                                    \
            int dk = 2 * r + (kk & 1);                                      \
            int kl = (((KS) & 1) << 4) + dk + ((kk & 2) ? 8 : 0);           \
            int x4 = 4 * (kl & 7);                                          \
            G[kk][0] = sa[kl * 128 + (ml0 ^ x4)];                           \
            G[kk][1] = sa[kl * 128 + (ml1 ^ x4)];                           \
        }                                                                   \
        __half2 en[4];                                                      \
        en[0] = s_eh[k0 + 2 * r];                                           \
        en[1] = s_eh[k0 + 2 * r + 1];                                       \
        en[2] = s_eh[k0 + 2 * r + 8];                                       \
        en[3] = s_eh[k0 + 2 * r + 9];                                       \
        __half2 w[4][2];                                                    \
        _Pragma("unroll")                                                   \
        for (int kk = 0; kk < 4; kk++) {                                    \
            _Pragma("unroll")                                               \
            for (int mm = 0; mm < 2; mm++) {                                \
                __half2 e = em_h2[mm];                                      \
                __half2 d = __hadd2(en[kk], e);                             \
                __half2 mn = __hmin2(en[kk], e);                            \
                __half2 a2 = __float2half2_rn(G[kk][mm]);                   \
                w[kk][mm] = __hmul2(__hmul2(mn, h2rcp(d)), a2);             \
            }                                                               \
        }                                                                   \
        uint32_t a0[4], a1[4];                                              \
        a0[0] = h2u(__lows2half2(w[0][0], w[1][0]));                        \
        a0[1] = h2u(__lows2half2(w[0][1], w[1][1]));                        \
        a0[2] = h2u(__lows2half2(w[2][0], w[3][0]));                        \
        a0[3] = h2u(__lows2half2(w[2][1], w[3][1]));                        \
        a1[0] = h2u(__highs2half2(w[0][0], w[1][0]));                       \
        a1[1] = h2u(__highs2half2(w[0][1], w[1][1]));                       \
        a1[2] = h2u(__highs2half2(w[2][0], w[3][0]));                       \
        a1[3] = h2u(__highs2half2(w[2][1], w[3][1]));                       \
        const int kp0 = (KS) * 8;                                           \
        const int off0 = (kp0 + r + 4 * q) & 31;                            \
        const int off4 = (kp0 + r + 4 + 4 * q) & 31;                        \
        _Pragma("unroll")                                                   \
        for (int cf = 0; cf < 4; cf++) {                                    \
            const int row = (cf * 8 + q) * 32;                              \
            uint32_t b00 = s_B[0][row + off0];                              \
            uint32_t b01 = s_B[0][row + off4];                              \
            uint32_t b10 = s_B[1][row + off0];                              \
            uint32_t b11 = s_B[1][row + off4];                              \
            MMA_F16(acc[0][cf], a0, b00, b01);                              \
            MMA_F16(acc[1][cf], a1, b10, b11);                              \
        }                                                                   \
    }

    // prologue: adj H0(chunk0) + fea chunk0
    STAGE_ADJ(0, 0, nbeg);
    CP_COMMIT();
    {
        float4 u[4];
        float ev0 = 0.f, ev1 = 0.f;
        STAGE_LOAD(u, ev0, ev1, nbeg);
        STAGE_STORE(u, ev0, ev1);
    }
    CP_WAIT0();
    __syncthreads();

    for (int n0 = nbeg; n0 < nend; n0 += KC) {
        const int n1 = n0 + KC;
        const bool has_next = (n1 < nend);

        // H1 of current chunk into adj buffer 1
        STAGE_ADJ(1, 1, n0);
        CP_COMMIT();

        float4 u[4];
        float ev0 = 0.f, ev1 = 0.f;
        if (has_next) STAGE_LOAD(u, ev0, ev1, n1);   // register prefetch

        COMPUTE_KS(0, 0);
        COMPUTE_KS(0, 1);

        CP_WAIT0();
        __syncthreads();          // adj buf1 ready; buf0 reads done

        if (has_next) {
            STAGE_ADJ(0, 0, n1);  // H0 of next chunk into adj buffer 0
            CP_COMMIT();
        }

        COMPUTE_KS(1, 2);
        COMPUTE_KS(1, 3);

        __syncthreads();          // all fea/s_eh reads done — safe to overwrite
        if (has_next) STAGE_STORE(u, ev0, ev1);
        CP_WAIT0();
        __syncthreads();          // next fea + next adj H0 ready
    }

#pragma unroll
    for (int bi = 0; bi < 2; bi++) {
        float* dst = g_part[z] + (((size_t)(2 * bp + bi) * C_) << 12);
#pragma unroll
        for (int cf = 0; cf < 4; cf++) {
            int c0 = cf * 8 + 2 * r;
            int m0 = mb + q;
            dst[((size_t)c0 << 12) + m0] = acc[bi][cf][0];
            dst[((size_t)(c0 + 1) << 12) + m0] = acc[bi][cf][1];
            dst[((size_t)c0 << 12) + m0 + 8] = acc[bi][cf][2];
            dst[((size_t)(c0 + 1) << 12) + m0 + 8] = acc[bi][cf][3];
        }
    }
}

__global__ void combine_kernel(const float* __restrict__ para,
                               float* __restrict__ out) {
    int idx = blockIdx.x * blockDim.x + threadIdx.x;
    const float4* pp = reinterpret_cast<const float4*>(para);
    float4 s = reinterpret_cast<const float4*>(g_part[0])[idx];
#pragma unroll
    for (int z = 1; z < SPLIT; z++) {
        float4 v = reinterpret_cast<const float4*>(g_part[z])[idx];
        s.x += v.x; s.y += v.y; s.z += v.z; s.w += v.w;
    }
    float4 pv = pp[idx & (C_ * N_ / 4 - 1)];
    float4 o;
    o.x = fmaxf(2.0f * s.x * pv.x, 0.f);
    o.y = fmaxf(2.0f * s.y * pv.y, 0.f);
    o.z = fmaxf(2.0f * s.z * pv.z, 0.f);
    o.w = fmaxf(2.0f * s.w * pv.w, 0.f);
    reinterpret_cast<float4*>(out)[idx] = o;
}

extern "C" void kernel_launch(void* const* d_in, const int* in_sizes, int n_in,
                              void* d_out, int out_size) {
    const float* x    = (const float*)d_in[0];  // [8,32,64,64]
    const float* para = (const float*)d_in[1];  // [1,32,64,64]
    const float* adj  = (const float*)d_in[2];  // [4096,4096]
    float* out = (float*)d_out;

    mean_exp_kernel<<<B_ * N_ / 4 / 128, 128>>>(x);

    dim3 grid(N_ / 128, B_ / 2, SPLIT);
    gcn_mma_kernel<<<grid, 256>>>(x, adj);

    combine_kernel<<<(B_ * C_ * N_ / 4) / 256, 256>>>(para, out);
}

// round 16
// speedup vs baseline: 1.4024x; 1.0865x over previous
#include <cuda_runtime.h>
#include <cuda_fp16.h>
#include <cstdint>

#define B_ 8
#define C_ 32
#define N_ 4096
#define KC 64
#define SPLIT 4

__device__ float g_e[B_ * N_];
__device__ float g_part[SPLIT][B_ * C_ * N_];

__global__ void mean_exp_kernel(const float* __restrict__ x) {
    int idx = blockIdx.x * blockDim.x + threadIdx.x;
    if (idx >= B_ * N_) return;
    int b = idx >> 12, n = idx & (N_ - 1);
    const float* p = x + ((size_t)b * C_) * N_ + n;
    float s = 0.f;
#pragma unroll
    for (int c = 0; c < C_; c++) s += p[(size_t)c * N_];
    g_e[idx] = __expf(s * (1.0f / C_));
}

__device__ __forceinline__ uint32_t pack_f16(float hi, float lo) {
    uint32_t d;
    asm("cvt.rn.f16x2.f32 %0, %1, %2;" : "=r"(d) : "f"(hi), "f"(lo));
    return d;
}
__device__ __forceinline__ uint32_t h2u(__half2 h) {
    return *reinterpret_cast<uint32_t*>(&h);
}
__device__ __forceinline__ void cp_async16(uint32_t saddr, const void* g) {
    asm volatile("cp.async.cg.shared.global [%0], [%1], 16;"
                 :: "r"(saddr), "l"(g) : "memory");
}
#define CP_COMMIT() asm volatile("cp.async.commit_group;" ::: "memory")
#define CP_WAIT0()  asm volatile("cp.async.wait_group 0;" ::: "memory")

__device__ __forceinline__ void ldsm_x4(uint32_t& r0, uint32_t& r1,
                                        uint32_t& r2, uint32_t& r3,
                                        uint32_t addr) {
    asm volatile("ldmatrix.sync.aligned.m8n8.x4.shared.b16 {%0,%1,%2,%3}, [%4];"
                 : "=r"(r0), "=r"(r1), "=r"(r2), "=r"(r3) : "r"(addr));
}

#define MMA_F16(acc, a, b0v, b1v)                                           \
    asm volatile(                                                           \
        "mma.sync.aligned.m16n8k16.row.col.f32.f16.f16.f32 "                \
        "{%0,%1,%2,%3}, {%4,%5,%6,%7}, {%8,%9}, {%0,%1,%2,%3};"             \
        : "+f"((acc)[0]), "+f"((acc)[1]), "+f"((acc)[2]), "+f"((acc)[3])    \
        : "r"((a)[0]), "r"((a)[1]), "r"((a)[2]), "r"((a)[3]),               \
          "r"(b0v), "r"(b1v))

__global__ __launch_bounds__(256, 2)
void gcn_mma_kernel(const float* __restrict__ x,
                    const float* __restrict__ adj) {
    __shared__ float s_adjf[2][32 * 128];    // [buf][row*128 + swz(col)]
    __shared__ uint32_t s_B[2][32 * 32];     // [batch][c*32 + swz(npair)]
    __shared__ __half2 s_eh[KC];             // [n] = (e_b0, e_b1)

    const int tid = threadIdx.x;
    const int warp = tid >> 5;
    const int lane = tid & 31;
    const int q = lane >> 2;
    const int r = lane & 3;
    const int mb_cta = blockIdx.x * 128;
    const int mb = mb_cta + warp * 16;
    const int ml0 = warp * 16 + q;
    const int ml1 = ml0 + 8;
    const int bp = blockIdx.y;
    const int b0 = 2 * bp, b1 = 2 * bp + 1;
    const int z = blockIdx.z;
    const int nbeg = z * (N_ / SPLIT);
    const int nend = nbeg + (N_ / SPLIT);

    uint32_t s_adj_addr, sB_addr;
    asm("{ .reg .u64 t; cvta.to.shared.u64 t, %1; cvt.u32.u64 %0, t; }"
        : "=r"(s_adj_addr) : "l"(s_adjf));
    asm("{ .reg .u64 t; cvta.to.shared.u64 t, %1; cvt.u32.u64 %0, t; }"
        : "=r"(sB_addr) : "l"(s_B));

    // LDSM lane geometry: matrix id m = lane>>3 → (cf_half = m>>1, h = m&1)
    const int lm_m = lane >> 3;
    const int lm_cl = lane & 7;
    const int lm_cf_half = lm_m >> 1;
    const int lm_h = lm_m & 1;
    const uint32_t lm_row0 = sB_addr + (uint32_t)((lm_cf_half * 8 + lm_cl) * 128);
    const int lm_wbase = lm_h * 4 + 4 * lm_cl;

    __half2 em_h2[2];
    em_h2[0] = __floats2half2_rn(g_e[b0 * N_ + mb + q],
                                 g_e[b1 * N_ + mb + q]);
    em_h2[1] = __floats2half2_rn(g_e[b0 * N_ + mb + q + 8],
                                 g_e[b1 * N_ + mb + q + 8]);

    float acc[2][4][4];
#pragma unroll
    for (int bi = 0; bi < 2; bi++)
#pragma unroll
        for (int cf = 0; cf < 4; cf++)
#pragma unroll
            for (int i = 0; i < 4; i++) acc[bi][cf][i] = 0.f;

    const int st_b = tid >> 7;
    const int st_c = (tid >> 2) & 31;
    const int st_p0 = (tid & 3) * 8;
    const float* st_x = x + (((size_t)(2 * bp + st_b) * C_ + st_c) << 12);
    const int st_sw = 4 * (st_c & 7);

#define STAGE_ADJ(BI, H, N0)                                                \
    {                                                                       \
        const float* gsrc = adj + (size_t)((N0) + (H) * 32) * N_ + mb_cta;  \
        uint32_t sb = s_adj_addr + (BI) * 16384;                            \
        _Pragma("unroll")                                                   \
        for (int i = 0; i < 4; i++) {                                       \
            int lin = tid + i * 256;                                        \
            int row = lin >> 5, c4 = lin & 31;                              \
            int col = c4 * 4;                                               \
            int sw = col ^ (4 * (row & 7));                                 \
            cp_async16(sb + (uint32_t)(row * 128 + sw) * 4,                 \
                       gsrc + (size_t)row * N_ + col);                      \
        }                                                                   \
    }

#define STAGE_STORE(U, EV0, EV1)                                            \
    {                                                                       \
        uint32_t* dst = &s_B[st_b][st_c * 32];                              \
        uint32_t pr[8];                                                     \
        _Pragma("unroll")                                                   \
        for (int j = 0; j < 4; j++) {                                       \
            pr[2 * j]     = pack_f16(U[j].y, U[j].x);                       \
            pr[2 * j + 1] = pack_f16(U[j].w, U[j].z);                       \
        }                                                                   \
        *reinterpret_cast<uint4*>(&dst[(st_p0 + st_sw) & 31]) =             \
            make_uint4(pr[0], pr[1], pr[2], pr[3]);                         \
        *reinterpret_cast<uint4*>(&dst[(st_p0 + 4 + st_sw) & 31]) =         \
            make_uint4(pr[4], pr[5], pr[6], pr[7]);                         \
        if (tid < KC) s_eh[tid] = __floats2half2_rn(EV0, EV1);              \
    }

#define STAGE_LOAD(U, EV0, EV1, NBASE)                                      \
    {                                                                       \
        _Pragma("unroll")                                                   \
        for (int j = 0; j < 4; j++)                                         \
            U[j] = *reinterpret_cast<const float4*>(                        \
                st_x + (NBASE) + st_p0 * 2 + 4 * j);                        \
        if (tid < KC) {                                                     \
            EV0 = g_e[b0 * N_ + (NBASE) + tid];                             \
            EV1 = g_e[b1 * N_ + (NBASE) + tid];                             \
        }                                                                   \
    }

#define COMPUTE_KS(BA, KS)                                                  \
    {                                                                       \
        const int k0 = (KS) * 16;                                           \
        const float* sa = s_adjf[BA];                                       \
        float G[4][2];                                                      \
        _Pragma("unroll")                                                   \
        for (int kk = 0; kk < 4; kk++) {                                    \
            int dk = 2 * r + (kk & 1);                                      \
            int kl = (((KS) & 1) << 4) + dk + ((kk & 2) ? 8 : 0);           \
            int x4 = 4 * (kl & 7);                                          \
            G[kk][0] = sa[kl * 128 + (ml0 ^ x4)];                           \
            G[kk][1] = sa[kl * 128 + (ml1 ^ x4)];                           \
        }                                                                   \
        __half2 en[4];                                                      \
        en[0] = s_eh[k0 + 2 * r];                                           \
        en[1] = s_eh[k0 + 2 * r + 1];                                       \
        en[2] = s_eh[k0 + 2 * r + 8];                                       \
        en[3] = s_eh[k0 + 2 * r + 9];                                       \
        __half2 w[4][2];                                                    \
        _Pragma("unroll")                                                   \
        for (int kk = 0; kk < 4; kk++) {                                    \
            _Pragma("unroll")                                               \
            for (int mm = 0; mm < 2; mm++) {                                \
                __half2 e = em_h2[mm];                                      \
                __half2 d = __hadd2(en[kk], e);                             \
                __half2 mn = __hmin2(en[kk], e);                            \
                __half2 a2 = __float2half2_rn(G[kk][mm]);                   \
                w[kk][mm] = __hmul2(__hmul2(mn, h2rcp(d)), a2);             \
            }                                                               \
        }                                                                   \
        uint32_t a0[4], a1[4];                                              \
        a0[0] = h2u(__lows2half2(w[0][0], w[1][0]));                        \
        a0[1] = h2u(__lows2half2(w[0][1], w[1][1]));                        \
        a0[2] = h2u(__lows2half2(w[2][0], w[3][0]));                        \
        a0[3] = h2u(__lows2half2(w[2][1], w[3][1]));                        \
        a1[0] = h2u(__highs2half2(w[0][0], w[1][0]));                       \
        a1[1] = h2u(__highs2half2(w[0][1], w[1][1]));                       \
        a1[2] = h2u(__highs2half2(w[2][0], w[3][0]));                       \
        a1[3] = h2u(__highs2half2(w[2][1], w[3][1]));                       \
        const uint32_t woff =                                               \
            (uint32_t)(((lm_wbase + (KS) * 8) & 31) * 4);                   \
        uint32_t f0, f1, f2, f3;                                            \
        ldsm_x4(f0, f1, f2, f3, lm_row0 + woff);                            \
        MMA_F16(acc[0][0], a0, f0, f1);                                     \
        MMA_F16(acc[0][1], a0, f2, f3);                                     \
        ldsm_x4(f0, f1, f2, f3, lm_row0 + 2048 + woff);                     \
        MMA_F16(acc[0][2], a0, f0, f1);                                     \
        MMA_F16(acc[0][3], a0, f2, f3);                                     \
        ldsm_x4(f0, f1, f2, f3, lm_row0 + 4096 + woff);                     \
        MMA_F16(acc[1][0], a1, f0, f1);                                     \
        MMA_F16(acc[1][1], a1, f2, f3);                                     \
        ldsm_x4(f0, f1, f2, f3, lm_row0 + 6144 + woff);                     \
        MMA_F16(acc[1][2], a1, f0, f1);                                     \
        MMA_F16(acc[1][3], a1, f2, f3);                                     \
    }

    STAGE_ADJ(0, 0, nbeg);
    CP_COMMIT();
    {
        float4 u[4];
        float ev0 = 0.f, ev1 = 0.f;
        STAGE_LOAD(u, ev0, ev1, nbeg);
        STAGE_STORE(u, ev0, ev1);
    }
    CP_WAIT0();
    __syncthreads();

    for (int n0 = nbeg; n0 < nend; n0 += KC) {
        const int n1 = n0 + KC;
        const bool has_next = (n1 < nend);

        STAGE_ADJ(1, 1, n0);
        CP_COMMIT();

        float4 u[4];
        float ev0 = 0.f, ev1 = 0.f;
        if (has_next) STAGE_LOAD(u, ev0, ev1, n1);

        COMPUTE_KS(0, 0);
        COMPUTE_KS(0, 1);

        CP_WAIT0();
        __syncthreads();

        if (has_next) {
            STAGE_ADJ(0, 0, n1);
            CP_COMMIT();
        }

        COMPUTE_KS(1, 2);
        COMPUTE_KS(1, 3);

        __syncthreads();
        if (has_next) STAGE_STORE(u, ev0, ev1);
        CP_WAIT0();
        __syncthreads();
    }

#pragma unroll
    for (int bi = 0; bi < 2; bi++) {
        float* dst = g_part[z] + (((size_t)(2 * bp + bi) * C_) << 12);
#pragma unroll
        for (int cf = 0; cf < 4; cf++) {
            int c0 = cf * 8 + 2 * r;
            int m0 = mb + q;
            dst[((size_t)c0 << 12) + m0] = acc[bi][cf][0];
            dst[((size_t)(c0 + 1) << 12) + m0] = acc[bi][cf][1];
            dst[((size_t)c0 << 12) + m0 + 8] = acc[bi][cf][2];
            dst[((size_t)(c0 + 1) << 12) + m0 + 8] = acc[bi][cf][3];
        }
    }
}

__global__ void combine_kernel(const float* __restrict__ para,
                               float* __restrict__ out) {
    int idx = blockIdx.x * blockDim.x + threadIdx.x;
    const float4* pp = reinterpret_cast<const float4*>(para);
    float4 s = reinterpret_cast<const float4*>(g_part[0])[idx];
#pragma unroll
    for (int z = 1; z < SPLIT; z++) {
        float4 v = reinterpret_cast<const float4*>(g_part[z])[idx];
        s.x += v.x; s.y += v.y; s.z += v.z; s.w += v.w;
    }
    float4 pv = pp[idx & (C_ * N_ / 4 - 1)];
    float4 o;
    o.x = fmaxf(2.0f * s.x * pv.x, 0.f);
    o.y = fmaxf(2.0f * s.y * pv.y, 0.f);
    o.z = fmaxf(2.0f * s.z * pv.z, 0.f);
    o.w = fmaxf(2.0f * s.w * pv.w, 0.f);
    reinterpret_cast<float4*>(out)[idx] = o;
}

extern "C" void kernel_launch(void* const* d_in, const int* in_sizes, int n_in,
                              void* d_out, int out_size) {
    const float* x    = (const float*)d_in[0];  // [8,32,64,64]
    const float* para = (const float*)d_in[1];  // [1,32,64,64]
    const float* adj  = (const float*)d_in[2];  // [4096,4096]
    float* out = (float*)d_out;

    mean_exp_kernel<<<(B_ * N_ + 127) / 128, 128>>>(x);

    dim3 grid(N_ / 128, B_ / 2, SPLIT);
    gcn_mma_kernel<<<grid, 256>>>(x, adj);

    combine_kernel<<<(B_ * C_ * N_ / 4) / 256, 256>>>(para, out);
}